// round 6
// baseline (speedup 1.0000x reference)
#include <cuda_runtime.h>
#include <cstdint>

#define BSZ 8
#define SEQ 1024
#define DIM 512
#define NHEAD 8
#define HDIM 64
#define NTOK (BSZ*SEQ)                 // 8192
#define NELEM ((size_t)NTOK*DIM)       // 4194304

// Intermediate scratch (static device globals; no allocations).
__device__ float g_q[NELEM];
__device__ float g_k[NELEM];
__device__ float g_v[NELEM];
__device__ float g_att[NELEM];
__device__ float g_ln0[NELEM];
__device__ float g_mid[NELEM];

// ---------------------------------------------------------------------------
// packed f32x2 helpers (Blackwell FFMA2 path — PTX only, ptxas never emits it)
// ---------------------------------------------------------------------------
typedef unsigned long long u64;

__device__ __forceinline__ u64 dup2(float v) {
    u64 r;
    asm("mov.b64 %0, {%1, %1};" : "=l"(r) : "f"(v));
    return r;
}
__device__ __forceinline__ void unpack2(u64 p, float& lo, float& hi) {
    asm("mov.b64 {%0, %1}, %2;" : "=f"(lo), "=f"(hi) : "l"(p));
}
__device__ __forceinline__ u64 fma2(u64 a, u64 b, u64 c) {
    u64 d;
    asm("fma.rn.f32x2 %0, %1, %2, %3;" : "=l"(d) : "l"(a), "l"(b), "l"(c));
    return d;
}
__device__ __forceinline__ u64 mul2(u64 a, u64 b) {
    u64 d;
    asm("mul.rn.f32x2 %0, %1, %2;" : "=l"(d) : "l"(a), "l"(b));
    return d;
}
__device__ __forceinline__ u64 add2(u64 a, u64 b) {
    u64 d;
    asm("add.rn.f32x2 %0, %1, %2;" : "=l"(d) : "l"(a), "l"(b));
    return d;
}

// ---------------------------------------------------------------------------
// cp.async helpers
// ---------------------------------------------------------------------------
__device__ __forceinline__ void cp16(void* smem_dst, const void* gmem_src) {
    unsigned int s = (unsigned int)__cvta_generic_to_shared(smem_dst);
    asm volatile("cp.async.cg.shared.global [%0], [%1], 16;"
                 :: "r"(s), "l"(gmem_src) : "memory");
}
__device__ __forceinline__ void cp_commit() {
    asm volatile("cp.async.commit_group;" ::: "memory");
}
__device__ __forceinline__ void cp_wait0() {
    asm volatile("cp.async.wait_group 0;" ::: "memory");
}
__device__ __forceinline__ void cp_wait1() {
    asm volatile("cp.async.wait_group 1;" ::: "memory");
}

// ---------------------------------------------------------------------------
// 128x128x16 fp32 tiled GEMM, 2-stage pipelined, FFMA2 microkernel.
// (unchanged from round 4 — proven 90us; acts as control)
// ---------------------------------------------------------------------------
template <int MODE>
__device__ __forceinline__ void gemm_body(const float* __restrict__ A,
                                          const float* __restrict__ W,
                                          const float* __restrict__ bias,
                                          const float* __restrict__ resid,
                                          float* __restrict__ C)
{
    const int K = DIM, N = DIM;
    __shared__ float As[2][16][128];
    __shared__ float Bs[2][16][128];

    const int row0 = blockIdx.y * 128;
    const int col0 = blockIdx.x * 128;
    const int tid  = threadIdx.x;          // 0..255
    const int tx   = tid & 15;
    const int ty   = tid >> 4;

    const int rA0  = tid >> 2;             // 0..63
    const int kqA0 = (tid & 3) * 4;
    const int rA1  = rA0 + 64;
    const int krB0 = tid >> 5;             // 0..7
    const int krB1 = krB0 + 8;
    const int cq   = tid & 31;

    u64 c2[8][4];
#pragma unroll
    for (int i = 0; i < 8; i++)
#pragma unroll
        for (int j = 0; j < 4; j++) c2[i][j] = 0ULL;

    float4 a0, a1;

    a0 = *(const float4*)(A + (size_t)(row0 + rA0) * K + kqA0);
    a1 = *(const float4*)(A + (size_t)(row0 + rA1) * K + kqA0);
    As[0][kqA0 + 0][rA0] = a0.x;
    As[0][kqA0 + 1][rA0] = a0.y;
    As[0][kqA0 + 2][rA0] = a0.z;
    As[0][kqA0 + 3][rA0] = a0.w;
    As[0][kqA0 + 0][rA1] = a1.x;
    As[0][kqA0 + 1][rA1] = a1.y;
    As[0][kqA0 + 2][rA1] = a1.z;
    As[0][kqA0 + 3][rA1] = a1.w;
    cp16(&Bs[0][krB0][cq * 4], W + (size_t)krB0 * N + col0 + cq * 4);
    cp16(&Bs[0][krB1][cq * 4], W + (size_t)krB1 * N + col0 + cq * 4);
    cp_commit();
    cp_wait0();
    __syncthreads();

    const int NIT = K / 16;   // 32
    for (int it = 0; it < NIT; ++it) {
        const int buf  = it & 1;
        const int nbuf = buf ^ 1;
        const int kn   = (it + 1) * 16;

        if (it < NIT - 1) {
            a0 = *(const float4*)(A + (size_t)(row0 + rA0) * K + kn + kqA0);
            a1 = *(const float4*)(A + (size_t)(row0 + rA1) * K + kn + kqA0);
            cp16(&Bs[nbuf][krB0][cq * 4], W + (size_t)(kn + krB0) * N + col0 + cq * 4);
            cp16(&Bs[nbuf][krB1][cq * 4], W + (size_t)(kn + krB1) * N + col0 + cq * 4);
            cp_commit();
        }

#pragma unroll
        for (int k = 0; k < 16; k++) {
            float4 av0 = *(((const float4*)&As[buf][k][0]) + ty);
            float4 av1 = *(((const float4*)&As[buf][k][0]) + ty + 16);
            const ulonglong2* brow = (const ulonglong2*)&Bs[buf][k][0];
            ulonglong2 b01 = brow[tx];
            ulonglong2 b23 = brow[tx + 16];
            u64 bp[4] = {b01.x, b01.y, b23.x, b23.y};
            u64 ad[8];
            ad[0] = dup2(av0.x); ad[1] = dup2(av0.y);
            ad[2] = dup2(av0.z); ad[3] = dup2(av0.w);
            ad[4] = dup2(av1.x); ad[5] = dup2(av1.y);
            ad[6] = dup2(av1.z); ad[7] = dup2(av1.w);
#pragma unroll
            for (int i = 0; i < 8; i++)
#pragma unroll
                for (int j = 0; j < 4; j++)
                    c2[i][j] = fma2(ad[i], bp[j], c2[i][j]);
        }

        if (it < NIT - 1) {
            As[nbuf][kqA0 + 0][rA0] = a0.x;
            As[nbuf][kqA0 + 1][rA0] = a0.y;
            As[nbuf][kqA0 + 2][rA0] = a0.z;
            As[nbuf][kqA0 + 3][rA0] = a0.w;
            As[nbuf][kqA0 + 0][rA1] = a1.x;
            As[nbuf][kqA0 + 1][rA1] = a1.y;
            As[nbuf][kqA0 + 2][rA1] = a1.z;
            As[nbuf][kqA0 + 3][rA1] = a1.w;
            cp_wait0();
        }
        __syncthreads();
    }

#pragma unroll
    for (int i = 0; i < 8; i++) {
        int grow = row0 + ((i < 4) ? (ty * 4 + i) : (ty * 4 + 64 + i - 4));
        float cf[8];
        unpack2(c2[i][0], cf[0], cf[1]);
        unpack2(c2[i][1], cf[2], cf[3]);
        unpack2(c2[i][2], cf[4], cf[5]);
        unpack2(c2[i][3], cf[6], cf[7]);
#pragma unroll
        for (int jh = 0; jh < 2; jh++) {
            int gcol = col0 + tx * 4 + jh * 64;
            float4 o;
            o.x = cf[jh * 4 + 0] + bias[gcol + 0];
            o.y = cf[jh * 4 + 1] + bias[gcol + 1];
            o.z = cf[jh * 4 + 2] + bias[gcol + 2];
            o.w = cf[jh * 4 + 3] + bias[gcol + 3];
            size_t gi = (size_t)grow * N + gcol;
            if (MODE == 1) {
                float4 r = *(const float4*)(resid + gi);
                o.x = r.x + fmaxf(o.x, 0.f);
                o.y = r.y + fmaxf(o.y, 0.f);
                o.z = r.z + fmaxf(o.z, 0.f);
                o.w = r.w + fmaxf(o.w, 0.f);
            }
            *(float4*)(C + gi) = o;
        }
    }
}

__global__ __launch_bounds__(256)
void qkv_gemm(const float* __restrict__ queries, const float* __restrict__ keys,
              const float* __restrict__ Wq, const float* __restrict__ bq,
              const float* __restrict__ Wk, const float* __restrict__ bk,
              const float* __restrict__ Wv, const float* __restrict__ bv)
{
    const float* A; const float* W; const float* bias; float* C;
    if (blockIdx.z == 0)      { A = queries; W = Wq; bias = bq; C = g_q; }
    else if (blockIdx.z == 1) { A = keys;    W = Wk; bias = bk; C = g_k; }
    else                      { A = keys;    W = Wv; bias = bv; C = g_v; }
    gemm_body<0>(A, W, bias, nullptr, C);
}

__global__ __launch_bounds__(256)
void o_gemm(const float* __restrict__ Wo, const float* __restrict__ bo)
{
    gemm_body<1>(g_ln0, Wo, bo, g_ln0, g_mid);
}

// ---------------------------------------------------------------------------
// Flash attention (round-4 structure, occupancy-tuned):
// one thread per (b,h,sq) row, d=64 in registers (packed f32x2).
// 32-key smem tiles (double-buffered cp.async), softmax in 16-key subtiles
// to keep s[] at 16 registers. __launch_bounds__(128,3) -> 3 blocks/SM.
// ---------------------------------------------------------------------------
#define TK 32
#define NT (SEQ / TK)   // 32

__global__ __launch_bounds__(128, 3)
void attn_kernel(const float* __restrict__ pres_q, const float* __restrict__ pres_k)
{
    const int bh = blockIdx.y;            // 0..63
    const int b  = bh >> 3;
    const int h  = bh & 7;
    const int sq = blockIdx.x * 128 + threadIdx.x;
    const int tid = threadIdx.x;

    __shared__ float Ks[2][TK * 64];
    __shared__ float Vs[2][TK * 64];
    __shared__ float pks[2][TK];

    // q row: 64 floats = 32 packed pairs
    const float* qrow = g_q + ((size_t)b * SEQ + sq) * DIM + h * HDIM;
    u64 q2[32];
#pragma unroll
    for (int i = 0; i < 16; i++) {
        ulonglong2 t = ((const ulonglong2*)qrow)[i];
        q2[2 * i]     = t.x;
        q2[2 * i + 1] = t.y;
    }

    const float INFC  = 1e38f;
    const float rs    = 0.04419417382415922f;   // 1/sqrt(512)
    const float presq = pres_q[b * SEQ + sq];
    const float aq = presq * rs;
    const float cqv = (1.f - presq) * INFC;

    u64 acc2[32];
#pragma unroll
    for (int i = 0; i < 32; i++) acc2[i] = 0ULL;
    float m = -1e38f, l = 0.f;

    const float* kbase = g_k + ((size_t)b * SEQ) * DIM + h * HDIM;
    const float* vbase = g_v + ((size_t)b * SEQ) * DIM + h * HDIM;
    const float* pkb   = pres_k + b * SEQ;

    auto issue_tile = [&](int t, int buf) {
        int k0 = t * TK;
#pragma unroll
        for (int i = 0; i < 4; i++) {
            int f  = tid + 128 * i;           // 0..511
            int j  = f >> 4;                  // 0..31
            int c4 = (f & 15) * 4;            // 0..60
            size_t go = (size_t)(k0 + j) * DIM + c4;
            cp16(&Ks[buf][j * 64 + c4], kbase + go);
            cp16(&Vs[buf][j * 64 + c4], vbase + go);
        }
        if (tid < 8) cp16(&pks[buf][tid * 4], pkb + k0 + tid * 4);
        cp_commit();
    };

    issue_tile(0, 0);
    issue_tile(1, 1);

    for (int t = 0; t < NT; ++t) {
        const int buf = t & 1;
        if (t == NT - 1) cp_wait0(); else cp_wait1();
        __syncthreads();

#pragma unroll
        for (int sub = 0; sub < 2; sub++) {
            // --- logits for 16 keys (32 FFMA2 each, two chains) ---
            float s[16];
#pragma unroll
            for (int j = 0; j < 16; j++) {
                const int jj = sub * 16 + j;
                const ulonglong2* kr = (const ulonglong2*)&Ks[buf][jj * 64];
                u64 sa = 0ULL, sb = 0ULL;
#pragma unroll
                for (int i = 0; i < 16; i++) {
                    ulonglong2 kk = kr[i];
                    sa = fma2(q2[2 * i],     kk.x, sa);
                    sb = fma2(q2[2 * i + 1], kk.y, sb);
                }
                float lo, hi;
                unpack2(add2(sa, sb), lo, hi);
                float sum = lo + hi;
                float l1  = aq * sum - cqv;
                float pkj = pks[buf][jj];
                s[j] = pkj * l1 - (1.f - pkj) * INFC;
            }

            // --- streaming softmax update ---
            float tm = s[0];
#pragma unroll
            for (int j = 1; j < 16; j++) tm = fmaxf(tm, s[j]);
            float mnew = fmaxf(m, tm);
            float fac  = __expf(m - mnew);
            m = mnew;
            l *= fac;
            u64 facd = dup2(fac);
#pragma unroll
            for (int i = 0; i < 32; i++) acc2[i] = mul2(acc2[i], facd);

#pragma unroll
            for (int j = 0; j < 16; j++) {
                const int jj = sub * 16 + j;
                float p = __expf(s[j] - m);
                l += p;
                u64 pd = dup2(p);
                const ulonglong2* vr = (const ulonglong2*)&Vs[buf][jj * 64];
#pragma unroll
                for (int i = 0; i < 16; i++) {
                    ulonglong2 vv = vr[i];
                    acc2[2 * i]     = fma2(pd, vv.x, acc2[2 * i]);
                    acc2[2 * i + 1] = fma2(pd, vv.y, acc2[2 * i + 1]);
                }
            }
        }

        __syncthreads();                 // all readers done before buf reuse
        if (t + 2 < NT) issue_tile(t + 2, buf);
    }

    float inv = 1.f / l;
    float* orow = g_att + ((size_t)b * SEQ + sq) * DIM + h * HDIM;
#pragma unroll
    for (int i = 0; i < 16; i++) {
        float a0, a1, a2, a3, q0, q1, q2f, q3;
        unpack2(acc2[2 * i],     a0, a1);
        unpack2(acc2[2 * i + 1], a2, a3);
        unpack2(q2[2 * i],       q0, q1);
        unpack2(q2[2 * i + 1],   q2f, q3);
        float4 o;
        o.x = q0  + a0 * inv;
        o.y = q1  + a1 * inv;
        o.z = q2f + a2 * inv;
        o.w = q3  + a3 * inv;
        ((float4*)orow)[i] = o;
    }
}

// ---------------------------------------------------------------------------
// LayerNorm over last dim (512). One block per row, 128 threads.
// ---------------------------------------------------------------------------
__device__ __forceinline__ void ln_body(const float* __restrict__ in,
                                        float* __restrict__ out,
                                        const float* __restrict__ g,
                                        const float* __restrict__ b)
{
    const int row = blockIdx.x;
    const int tid = threadIdx.x;
    const float* x = in + (size_t)row * DIM;

    float v[4];
#pragma unroll
    for (int i = 0; i < 4; i++) v[i] = x[tid + i * 128];

    float s = v[0] + v[1] + v[2] + v[3];
#pragma unroll
    for (int o = 16; o > 0; o >>= 1) s += __shfl_xor_sync(0xffffffffu, s, o);
    __shared__ float red1[4];
    __shared__ float red2[4];
    int wid = tid >> 5;
    if ((tid & 31) == 0) red1[wid] = s;
    __syncthreads();
    float mu = (red1[0] + red1[1] + red1[2] + red1[3]) * (1.f / DIM);

    float q = 0.f;
#pragma unroll
    for (int i = 0; i < 4; i++) { float d = v[i] - mu; q += d * d; }
#pragma unroll
    for (int o = 16; o > 0; o >>= 1) q += __shfl_xor_sync(0xffffffffu, q, o);
    if ((tid & 31) == 0) red2[wid] = q;
    __syncthreads();
    float var  = (red2[0] + red2[1] + red2[2] + red2[3]) * (1.f / DIM);
    float rstd = rsqrtf(var + 1e-5f);

#pragma unroll
    for (int i = 0; i < 4; i++) {
        int c = tid + i * 128;
        out[(size_t)row * DIM + c] = (v[i] - mu) * rstd * g[c] + b[c];
    }
}

__global__ __launch_bounds__(128)
void ln0_kernel(const float* __restrict__ g0, const float* __restrict__ b0)
{
    ln_body(g_att, g_ln0, g0, b0);
}

__global__ __launch_bounds__(128)
void ln1_kernel(const float* __restrict__ g1, const float* __restrict__ b1,
                float* __restrict__ out)
{
    ln_body(g_mid, out, g1, b1);
}

// ---------------------------------------------------------------------------
extern "C" void kernel_launch(void* const* d_in, const int* in_sizes, int n_in,
                              void* d_out, int out_size)
{
    const float* queries = (const float*)d_in[0];
    const float* keys    = (const float*)d_in[1];
    const float* pq      = (const float*)d_in[2];
    const float* pk      = (const float*)d_in[3];

    int base = 4;
    if (n_in >= 5 && in_sizes[4] == 1) base = 5;

    const float* Wq = (const float*)d_in[base + 0];
    const float* bq = (const float*)d_in[base + 1];
    const float* Wk = (const float*)d_in[base + 2];
    const float* bk = (const float*)d_in[base + 3];
    const float* Wv = (const float*)d_in[base + 4];
    const float* bv = (const float*)d_in[base + 5];
    const float* Wo = (const float*)d_in[base + 6];
    const float* bo = (const float*)d_in[base + 7];
    const float* g0 = (const float*)d_in[base + 8];
    const float* b0 = (const float*)d_in[base + 9];
    const float* g1 = (const float*)d_in[base + 10];
    const float* b1 = (const float*)d_in[base + 11];
    float* out = (float*)d_out;

    qkv_gemm<<<dim3(DIM / 128, NTOK / 128, 3), 256>>>(queries, keys,
                                                      Wq, bq, Wk, bk, Wv, bv);
    attn_kernel<<<dim3(SEQ / 128, BSZ * NHEAD), 128>>>(pq, pk);
    ln0_kernel<<<NTOK, 128>>>(g0, b0);
    o_gemm<<<dim3(DIM / 128, NTOK / 128), 256>>>(Wo, bo);
    ln1_kernel<<<NTOK, 128>>>(g1, b1, out);
}

// round 7
// speedup vs baseline: 1.5044x; 1.5044x over previous
#include <cuda_runtime.h>
#include <cstdint>

#define BSZ 8
#define SEQ 1024
#define DIM 512
#define NHEAD 8
#define HDIM 64
#define NTOK (BSZ*SEQ)                 // 8192
#define NELEM ((size_t)NTOK*DIM)       // 4194304

// Intermediate scratch (static device globals; no allocations).
__device__ float g_q[NELEM];
__device__ float g_k[NELEM];
__device__ float g_v[NELEM];
__device__ float g_att[NELEM];
__device__ float g_ln0[NELEM];
__device__ float g_mid[NELEM];

// ---------------------------------------------------------------------------
// packed f32x2 helpers (Blackwell FFMA2 path — PTX only, ptxas never emits it)
// ---------------------------------------------------------------------------
typedef unsigned long long u64;

__device__ __forceinline__ u64 dup2(float v) {
    u64 r;
    asm("mov.b64 %0, {%1, %1};" : "=l"(r) : "f"(v));
    return r;
}
__device__ __forceinline__ void unpack2(u64 p, float& lo, float& hi) {
    asm("mov.b64 {%0, %1}, %2;" : "=f"(lo), "=f"(hi) : "l"(p));
}
__device__ __forceinline__ u64 fma2(u64 a, u64 b, u64 c) {
    u64 d;
    asm("fma.rn.f32x2 %0, %1, %2, %3;" : "=l"(d) : "l"(a), "l"(b), "l"(c));
    return d;
}
__device__ __forceinline__ u64 mul2(u64 a, u64 b) {
    u64 d;
    asm("mul.rn.f32x2 %0, %1, %2;" : "=l"(d) : "l"(a), "l"(b));
    return d;
}
__device__ __forceinline__ u64 add2(u64 a, u64 b) {
    u64 d;
    asm("add.rn.f32x2 %0, %1, %2;" : "=l"(d) : "l"(a), "l"(b));
    return d;
}

// ---------------------------------------------------------------------------
// cp.async helpers
// ---------------------------------------------------------------------------
__device__ __forceinline__ void cp16(void* smem_dst, const void* gmem_src) {
    unsigned int s = (unsigned int)__cvta_generic_to_shared(smem_dst);
    asm volatile("cp.async.cg.shared.global [%0], [%1], 16;"
                 :: "r"(s), "l"(gmem_src) : "memory");
}
__device__ __forceinline__ void cp_commit() {
    asm volatile("cp.async.commit_group;" ::: "memory");
}
__device__ __forceinline__ void cp_wait0() {
    asm volatile("cp.async.wait_group 0;" ::: "memory");
}
__device__ __forceinline__ void cp_wait1() {
    asm volatile("cp.async.wait_group 1;" ::: "memory");
}

// ---------------------------------------------------------------------------
// 128x128x16 fp32 tiled GEMM, 2-stage pipelined, FFMA2 microkernel.
// (round-4 proven version, unchanged)
// ---------------------------------------------------------------------------
template <int MODE>
__device__ __forceinline__ void gemm_body(const float* __restrict__ A,
                                          const float* __restrict__ W,
                                          const float* __restrict__ bias,
                                          const float* __restrict__ resid,
                                          float* __restrict__ C)
{
    const int K = DIM, N = DIM;
    __shared__ float As[2][16][128];
    __shared__ float Bs[2][16][128];

    const int row0 = blockIdx.y * 128;
    const int col0 = blockIdx.x * 128;
    const int tid  = threadIdx.x;          // 0..255
    const int tx   = tid & 15;
    const int ty   = tid >> 4;

    const int rA0  = tid >> 2;             // 0..63
    const int kqA0 = (tid & 3) * 4;
    const int rA1  = rA0 + 64;
    const int krB0 = tid >> 5;             // 0..7
    const int krB1 = krB0 + 8;
    const int cq   = tid & 31;

    u64 c2[8][4];
#pragma unroll
    for (int i = 0; i < 8; i++)
#pragma unroll
        for (int j = 0; j < 4; j++) c2[i][j] = 0ULL;

    float4 a0, a1;

    a0 = *(const float4*)(A + (size_t)(row0 + rA0) * K + kqA0);
    a1 = *(const float4*)(A + (size_t)(row0 + rA1) * K + kqA0);
    As[0][kqA0 + 0][rA0] = a0.x;
    As[0][kqA0 + 1][rA0] = a0.y;
    As[0][kqA0 + 2][rA0] = a0.z;
    As[0][kqA0 + 3][rA0] = a0.w;
    As[0][kqA0 + 0][rA1] = a1.x;
    As[0][kqA0 + 1][rA1] = a1.y;
    As[0][kqA0 + 2][rA1] = a1.z;
    As[0][kqA0 + 3][rA1] = a1.w;
    cp16(&Bs[0][krB0][cq * 4], W + (size_t)krB0 * N + col0 + cq * 4);
    cp16(&Bs[0][krB1][cq * 4], W + (size_t)krB1 * N + col0 + cq * 4);
    cp_commit();
    cp_wait0();
    __syncthreads();

    const int NIT = K / 16;   // 32
    for (int it = 0; it < NIT; ++it) {
        const int buf  = it & 1;
        const int nbuf = buf ^ 1;
        const int kn   = (it + 1) * 16;

        if (it < NIT - 1) {
            a0 = *(const float4*)(A + (size_t)(row0 + rA0) * K + kn + kqA0);
            a1 = *(const float4*)(A + (size_t)(row0 + rA1) * K + kn + kqA0);
            cp16(&Bs[nbuf][krB0][cq * 4], W + (size_t)(kn + krB0) * N + col0 + cq * 4);
            cp16(&Bs[nbuf][krB1][cq * 4], W + (size_t)(kn + krB1) * N + col0 + cq * 4);
            cp_commit();
        }

#pragma unroll
        for (int k = 0; k < 16; k++) {
            float4 av0 = *(((const float4*)&As[buf][k][0]) + ty);
            float4 av1 = *(((const float4*)&As[buf][k][0]) + ty + 16);
            const ulonglong2* brow = (const ulonglong2*)&Bs[buf][k][0];
            ulonglong2 b01 = brow[tx];
            ulonglong2 b23 = brow[tx + 16];
            u64 bp[4] = {b01.x, b01.y, b23.x, b23.y};
            u64 ad[8];
            ad[0] = dup2(av0.x); ad[1] = dup2(av0.y);
            ad[2] = dup2(av0.z); ad[3] = dup2(av0.w);
            ad[4] = dup2(av1.x); ad[5] = dup2(av1.y);
            ad[6] = dup2(av1.z); ad[7] = dup2(av1.w);
#pragma unroll
            for (int i = 0; i < 8; i++)
#pragma unroll
                for (int j = 0; j < 4; j++)
                    c2[i][j] = fma2(ad[i], bp[j], c2[i][j]);
        }

        if (it < NIT - 1) {
            As[nbuf][kqA0 + 0][rA0] = a0.x;
            As[nbuf][kqA0 + 1][rA0] = a0.y;
            As[nbuf][kqA0 + 2][rA0] = a0.z;
            As[nbuf][kqA0 + 3][rA0] = a0.w;
            As[nbuf][kqA0 + 0][rA1] = a1.x;
            As[nbuf][kqA0 + 1][rA1] = a1.y;
            As[nbuf][kqA0 + 2][rA1] = a1.z;
            As[nbuf][kqA0 + 3][rA1] = a1.w;
            cp_wait0();
        }
        __syncthreads();
    }

#pragma unroll
    for (int i = 0; i < 8; i++) {
        int grow = row0 + ((i < 4) ? (ty * 4 + i) : (ty * 4 + 64 + i - 4));
        float cf[8];
        unpack2(c2[i][0], cf[0], cf[1]);
        unpack2(c2[i][1], cf[2], cf[3]);
        unpack2(c2[i][2], cf[4], cf[5]);
        unpack2(c2[i][3], cf[6], cf[7]);
#pragma unroll
        for (int jh = 0; jh < 2; jh++) {
            int gcol = col0 + tx * 4 + jh * 64;
            float4 o;
            o.x = cf[jh * 4 + 0] + bias[gcol + 0];
            o.y = cf[jh * 4 + 1] + bias[gcol + 1];
            o.z = cf[jh * 4 + 2] + bias[gcol + 2];
            o.w = cf[jh * 4 + 3] + bias[gcol + 3];
            size_t gi = (size_t)grow * N + gcol;
            if (MODE == 1) {
                float4 r = *(const float4*)(resid + gi);
                o.x = r.x + fmaxf(o.x, 0.f);
                o.y = r.y + fmaxf(o.y, 0.f);
                o.z = r.z + fmaxf(o.z, 0.f);
                o.w = r.w + fmaxf(o.w, 0.f);
            }
            *(float4*)(C + gi) = o;
        }
    }
}

__global__ __launch_bounds__(256)
void qkv_gemm(const float* __restrict__ queries, const float* __restrict__ keys,
              const float* __restrict__ Wq, const float* __restrict__ bq,
              const float* __restrict__ Wk, const float* __restrict__ bk,
              const float* __restrict__ Wv, const float* __restrict__ bv)
{
    const float* A; const float* W; const float* bias; float* C;
    if (blockIdx.z == 0)      { A = queries; W = Wq; bias = bq; C = g_q; }
    else if (blockIdx.z == 1) { A = keys;    W = Wk; bias = bk; C = g_k; }
    else                      { A = keys;    W = Wv; bias = bv; C = g_v; }
    gemm_body<0>(A, W, bias, nullptr, C);
}

__global__ __launch_bounds__(256)
void o_gemm(const float* __restrict__ Wo, const float* __restrict__ bo)
{
    gemm_body<1>(g_ln0, Wo, bo, g_ln0, g_mid);
}

// ---------------------------------------------------------------------------
// Flash attention (round-4 structure): one thread per (b,h,sq) row,
// d=64 in registers (packed f32x2), 32-key tiles, 2-stage cp.async.
// NEW: warp-uniform rescale skip — when no lane's running max changed,
// fac==1.0 and the rescale is an exact no-op; skip it (bit-identical).
// ---------------------------------------------------------------------------
#define TK 32
#define NT (SEQ / TK)   // 32

__global__ __launch_bounds__(128, 2)
void attn_kernel(const float* __restrict__ pres_q, const float* __restrict__ pres_k)
{
    const int bh = blockIdx.y;            // 0..63
    const int b  = bh >> 3;
    const int h  = bh & 7;
    const int sq = blockIdx.x * 128 + threadIdx.x;
    const int tid = threadIdx.x;

    __shared__ float Ks[2][TK * 64];
    __shared__ float Vs[2][TK * 64];
    __shared__ float pks[2][TK];

    // q row: 64 floats = 32 packed pairs
    const float* qrow = g_q + ((size_t)b * SEQ + sq) * DIM + h * HDIM;
    u64 q2[32];
#pragma unroll
    for (int i = 0; i < 16; i++) {
        ulonglong2 t = ((const ulonglong2*)qrow)[i];
        q2[2 * i]     = t.x;
        q2[2 * i + 1] = t.y;
    }

    const float INFC  = 1e38f;
    const float rs    = 0.04419417382415922f;   // 1/sqrt(512)
    const float presq = pres_q[b * SEQ + sq];
    const float aq = presq * rs;
    const float cqv = (1.f - presq) * INFC;

    u64 acc2[32];
#pragma unroll
    for (int i = 0; i < 32; i++) acc2[i] = 0ULL;
    float m = -1e38f, l = 0.f;

    const float* kbase = g_k + ((size_t)b * SEQ) * DIM + h * HDIM;
    const float* vbase = g_v + ((size_t)b * SEQ) * DIM + h * HDIM;
    const float* pkb   = pres_k + b * SEQ;

    auto issue_tile = [&](int t, int buf) {
        int k0 = t * TK;
#pragma unroll
        for (int i = 0; i < 4; i++) {
            int f  = tid + 128 * i;           // 0..511
            int j  = f >> 4;                  // 0..31
            int c4 = (f & 15) * 4;            // 0..60
            size_t go = (size_t)(k0 + j) * DIM + c4;
            cp16(&Ks[buf][j * 64 + c4], kbase + go);
            cp16(&Vs[buf][j * 64 + c4], vbase + go);
        }
        if (tid < 8) cp16(&pks[buf][tid * 4], pkb + k0 + tid * 4);
        cp_commit();
    };

    issue_tile(0, 0);
    issue_tile(1, 1);

    for (int t = 0; t < NT; ++t) {
        const int buf = t & 1;
        if (t == NT - 1) cp_wait0(); else cp_wait1();
        __syncthreads();

        // --- logits for 32 keys (32 FFMA2 each, two chains) ---
        float s[TK];
#pragma unroll
        for (int j = 0; j < TK; j++) {
            const ulonglong2* kr = (const ulonglong2*)&Ks[buf][j * 64];
            u64 sa = 0ULL, sb = 0ULL;
#pragma unroll
            for (int i = 0; i < 16; i++) {
                ulonglong2 kk = kr[i];
                sa = fma2(q2[2 * i],     kk.x, sa);
                sb = fma2(q2[2 * i + 1], kk.y, sb);
            }
            float lo, hi;
            unpack2(add2(sa, sb), lo, hi);
            float sum = lo + hi;
            float l1  = aq * sum - cqv;
            float pkj = pks[buf][j];
            s[j] = pkj * l1 - (1.f - pkj) * INFC;
        }

        // --- streaming softmax update ---
        float tm = s[0];
#pragma unroll
        for (int j = 1; j < TK; j++) tm = fmaxf(tm, s[j]);
        float mnew = fmaxf(m, tm);

        // warp-uniform skip: if no lane's max changed, fac==1 exactly and
        // the rescale (acc*=1, l*=1) is a bit-exact no-op.
        bool changed = (mnew != m);
        if (__any_sync(0xffffffffu, changed)) {
            float fac = __expf(m - mnew);
            m = mnew;
            l *= fac;
            u64 facd = dup2(fac);
#pragma unroll
            for (int i = 0; i < 32; i++) acc2[i] = mul2(acc2[i], facd);
        }

#pragma unroll
        for (int j = 0; j < TK; j++) {
            float p = __expf(s[j] - m);
            l += p;
            u64 pd = dup2(p);
            const ulonglong2* vr = (const ulonglong2*)&Vs[buf][j * 64];
#pragma unroll
            for (int i = 0; i < 16; i++) {
                ulonglong2 vv = vr[i];
                acc2[2 * i]     = fma2(pd, vv.x, acc2[2 * i]);
                acc2[2 * i + 1] = fma2(pd, vv.y, acc2[2 * i + 1]);
            }
        }

        __syncthreads();                 // all readers done before buf reuse
        if (t + 2 < NT) issue_tile(t + 2, buf);
    }

    float inv = 1.f / l;
    float* orow = g_att + ((size_t)b * SEQ + sq) * DIM + h * HDIM;
#pragma unroll
    for (int i = 0; i < 16; i++) {
        float a0, a1, a2, a3, q0, q1, q2f, q3;
        unpack2(acc2[2 * i],     a0, a1);
        unpack2(acc2[2 * i + 1], a2, a3);
        unpack2(q2[2 * i],       q0, q1);
        unpack2(q2[2 * i + 1],   q2f, q3);
        float4 o;
        o.x = q0  + a0 * inv;
        o.y = q1  + a1 * inv;
        o.z = q2f + a2 * inv;
        o.w = q3  + a3 * inv;
        ((float4*)orow)[i] = o;
    }
}

// ---------------------------------------------------------------------------
// LayerNorm over last dim (512). One block per row, 128 threads.
// ---------------------------------------------------------------------------
__device__ __forceinline__ void ln_body(const float* __restrict__ in,
                                        float* __restrict__ out,
                                        const float* __restrict__ g,
                                        const float* __restrict__ b)
{
    const int row = blockIdx.x;
    const int tid = threadIdx.x;
    const float* x = in + (size_t)row * DIM;

    float v[4];
#pragma unroll
    for (int i = 0; i < 4; i++) v[i] = x[tid + i * 128];

    float s = v[0] + v[1] + v[2] + v[3];
#pragma unroll
    for (int o = 16; o > 0; o >>= 1) s += __shfl_xor_sync(0xffffffffu, s, o);
    __shared__ float red1[4];
    __shared__ float red2[4];
    int wid = tid >> 5;
    if ((tid & 31) == 0) red1[wid] = s;
    __syncthreads();
    float mu = (red1[0] + red1[1] + red1[2] + red1[3]) * (1.f / DIM);

    float q = 0.f;
#pragma unroll
    for (int i = 0; i < 4; i++) { float d = v[i] - mu; q += d * d; }
#pragma unroll
    for (int o = 16; o > 0; o >>= 1) q += __shfl_xor_sync(0xffffffffu, q, o);
    if ((tid & 31) == 0) red2[wid] = q;
    __syncthreads();
    float var  = (red2[0] + red2[1] + red2[2] + red2[3]) * (1.f / DIM);
    float rstd = rsqrtf(var + 1e-5f);

#pragma unroll
    for (int i = 0; i < 4; i++) {
        int c = tid + i * 128;
        out[(size_t)row * DIM + c] = (v[i] - mu) * rstd * g[c] + b[c];
    }
}

__global__ __launch_bounds__(128)
void ln0_kernel(const float* __restrict__ g0, const float* __restrict__ b0)
{
    ln_body(g_att, g_ln0, g0, b0);
}

__global__ __launch_bounds__(128)
void ln1_kernel(const float* __restrict__ g1, const float* __restrict__ b1,
                float* __restrict__ out)
{
    ln_body(g_mid, out, g1, b1);
}

// ---------------------------------------------------------------------------
extern "C" void kernel_launch(void* const* d_in, const int* in_sizes, int n_in,
                              void* d_out, int out_size)
{
    const float* queries = (const float*)d_in[0];
    const float* keys    = (const float*)d_in[1];
    const float* pq      = (const float*)d_in[2];
    const float* pk      = (const float*)d_in[3];

    int base = 4;
    if (n_in >= 5 && in_sizes[4] == 1) base = 5;

    const float* Wq = (const float*)d_in[base + 0];
    const float* bq = (const float*)d_in[base + 1];
    const float* Wk = (const float*)d_in[base + 2];
    const float* bk = (const float*)d_in[base + 3];
    const float* Wv = (const float*)d_in[base + 4];
    const float* bv = (const float*)d_in[base + 5];
    const float* Wo = (const float*)d_in[base + 6];
    const float* bo = (const float*)d_in[base + 7];
    const float* g0 = (const float*)d_in[base + 8];
    const float* b0 = (const float*)d_in[base + 9];
    const float* g1 = (const float*)d_in[base + 10];
    const float* b1 = (const float*)d_in[base + 11];
    float* out = (float*)d_out;

    qkv_gemm<<<dim3(DIM / 128, NTOK / 128, 3), 256>>>(queries, keys,
                                                      Wq, bq, Wk, bk, Wv, bv);
    attn_kernel<<<dim3(SEQ / 128, BSZ * NHEAD), 128>>>(pq, pk);
    ln0_kernel<<<NTOK, 128>>>(g0, b0);
    o_gemm<<<dim3(DIM / 128, NTOK / 128), 256>>>(Wo, bo);
    ln1_kernel<<<NTOK, 128>>>(g1, b1, out);
}

// round 9
// speedup vs baseline: 1.6843x; 1.1196x over previous
#include <cuda_runtime.h>
#include <cuda_bf16.h>
#include <cstdint>

#define BSZ 8
#define SEQ 1024
#define DIM 512
#define NHEAD 8
#define HDIM 64
#define NTOK (BSZ*SEQ)                 // 8192
#define NELEM ((size_t)NTOK*DIM)       // 4194304

// fp32 intermediates
__device__ float g_q[NELEM];
__device__ float g_k[NELEM];
__device__ float g_v[NELEM];
__device__ float g_att[NELEM];
__device__ float g_ln0[NELEM];
__device__ float g_mid[NELEM];

// bf16 split planes, ROW-MAJOR. uint2 = 4 bf16.
__device__ uint2 g_qah[NELEM/4], g_qal[NELEM/4];
__device__ uint2 g_kah[NELEM/4], g_kal[NELEM/4];
__device__ uint2 g_lnh[NELEM/4], g_lnl[NELEM/4];
__device__ uint2 g_wph[4*DIM*DIM/4], g_wpl[4*DIM*DIM/4];   // B[n][k] = W[k][n]

typedef unsigned long long u64;

// ---------------------------------------------------------------------------
// packed f32x2 helpers (attention FFMA2 path)
// ---------------------------------------------------------------------------
__device__ __forceinline__ u64 dup2(float v) {
    u64 r; asm("mov.b64 %0, {%1, %1};" : "=l"(r) : "f"(v)); return r;
}
__device__ __forceinline__ void unpack2(u64 p, float& lo, float& hi) {
    asm("mov.b64 {%0, %1}, %2;" : "=f"(lo), "=f"(hi) : "l"(p));
}
__device__ __forceinline__ u64 fma2(u64 a, u64 b, u64 c) {
    u64 d; asm("fma.rn.f32x2 %0, %1, %2, %3;" : "=l"(d) : "l"(a), "l"(b), "l"(c)); return d;
}
__device__ __forceinline__ u64 mul2(u64 a, u64 b) {
    u64 d; asm("mul.rn.f32x2 %0, %1, %2;" : "=l"(d) : "l"(a), "l"(b)); return d;
}
__device__ __forceinline__ u64 add2(u64 a, u64 b) {
    u64 d; asm("add.rn.f32x2 %0, %1, %2;" : "=l"(d) : "l"(a), "l"(b)); return d;
}

// ---------------------------------------------------------------------------
// cp.async helpers
// ---------------------------------------------------------------------------
__device__ __forceinline__ void cp16(void* smem_dst, const void* gmem_src) {
    unsigned int s = (unsigned int)__cvta_generic_to_shared(smem_dst);
    asm volatile("cp.async.cg.shared.global [%0], [%1], 16;"
                 :: "r"(s), "l"(gmem_src) : "memory");
}
__device__ __forceinline__ void cp16u(unsigned int saddr, const void* gmem_src) {
    asm volatile("cp.async.cg.shared.global [%0], [%1], 16;"
                 :: "r"(saddr), "l"(gmem_src) : "memory");
}
__device__ __forceinline__ void cp_commit() {
    asm volatile("cp.async.commit_group;" ::: "memory");
}
__device__ __forceinline__ void cp_wait0() {
    asm volatile("cp.async.wait_group 0;" ::: "memory");
}
__device__ __forceinline__ void cp_wait1() {
    asm volatile("cp.async.wait_group 1;" ::: "memory");
}
__device__ __forceinline__ unsigned smem_u32(const void* p) {
    unsigned r;
    asm("{ .reg .u64 t; cvta.to.shared.u64 t, %1; cvt.u32.u64 %0, t; }"
        : "=r"(r) : "l"(p));
    return r;
}

// ---------------------------------------------------------------------------
// warp-level bf16 MMA (sm_80+ instruction, valid on base sm_103 target)
// D(16x8,f32) += A(16x16,bf16 row) * B(16x8,bf16 col)
// ---------------------------------------------------------------------------
__device__ __forceinline__ void mma16816(float* d, const unsigned* a, const unsigned* b) {
    asm volatile(
        "mma.sync.aligned.m16n8k16.row.col.f32.bf16.bf16.f32 "
        "{%0,%1,%2,%3}, {%4,%5,%6,%7}, {%8,%9}, {%0,%1,%2,%3};"
        : "+f"(d[0]), "+f"(d[1]), "+f"(d[2]), "+f"(d[3])
        : "r"(a[0]), "r"(a[1]), "r"(a[2]), "r"(a[3]), "r"(b[0]), "r"(b[1]));
}

// bf16 split of a float4 into hi/lo uint2
__device__ __forceinline__ void split4(float4 x, uint2& h, uint2& l) {
    __nv_bfloat162 h0 = __floats2bfloat162_rn(x.x, x.y);
    __nv_bfloat162 h1 = __floats2bfloat162_rn(x.z, x.w);
    float r0 = x.x - __bfloat162float(__low2bfloat16(h0));
    float r1 = x.y - __bfloat162float(__high2bfloat16(h0));
    float r2 = x.z - __bfloat162float(__low2bfloat16(h1));
    float r3 = x.w - __bfloat162float(__high2bfloat16(h1));
    __nv_bfloat162 l0 = __floats2bfloat162_rn(r0, r1);
    __nv_bfloat162 l1 = __floats2bfloat162_rn(r2, r3);
    h = make_uint2(*(unsigned*)&h0, *(unsigned*)&h1);
    l = make_uint2(*(unsigned*)&l0, *(unsigned*)&l1);
}

// ---------------------------------------------------------------------------
// convert_a: fp32 [8192,512] -> row-major bf16 hi/lo planes
// ---------------------------------------------------------------------------
__global__ __launch_bounds__(256)
void convert_a(const float* __restrict__ A, int dst)
{
    uint2* H = dst ? g_kah : g_qah;
    uint2* L = dst ? g_kal : g_qal;
    size_t i = (size_t)blockIdx.x * 256 + threadIdx.x;   // uint2 index
    float4 x = ((const float4*)A)[i];
    uint2 h, l;
    split4(x, h, l);
    H[i] = h;
    L[i] = l;
}

// ---------------------------------------------------------------------------
// convert_w: W[512,512] fp32 -> B[n][k]=W[k][n] bf16 hi/lo planes
// ---------------------------------------------------------------------------
__global__ __launch_bounds__(256)
void convert_w(const float* __restrict__ Wq, const float* __restrict__ Wk,
               const float* __restrict__ Wv, const float* __restrict__ Wo)
{
    const int mat = blockIdx.y;
    const float* W = (mat == 0) ? Wq : (mat == 1) ? Wk : (mat == 2) ? Wv : Wo;
    int o = blockIdx.x * 256 + threadIdx.x;   // uint2 index within matrix (65536)
    int n  = o >> 7;
    int k0 = (o & 127) * 4;
    float4 x;
    x.x = W[(size_t)(k0 + 0) * DIM + n];
    x.y = W[(size_t)(k0 + 1) * DIM + n];
    x.z = W[(size_t)(k0 + 2) * DIM + n];
    x.w = W[(size_t)(k0 + 3) * DIM + n];
    uint2 h, l;
    split4(x, h, l);
    g_wph[(size_t)mat * 65536 + o] = h;
    g_wpl[(size_t)mat * 65536 + o] = l;
}

// ---------------------------------------------------------------------------
// Tensor-core GEMM: C[128,128] per block via mma.sync bf16 3-term split.
// 256 thr = 8 warps (4m x 2n), warp tile 32x64, K-step 16, double-buffered.
// smem row stride 48B (conflict-free cp.async stores + fragment LDS).
// which: 0=q, 1=k, 2=v, 3=o (resid + relu epilogue)
// ---------------------------------------------------------------------------
__global__ __launch_bounds__(256)
void mma_gemm(int which, const float* __restrict__ bias)
{
    const uint2 *Ah, *Al; float* C;
    const float* resid = nullptr; int mode = 0;
    if (which == 0)      { Ah = g_qah; Al = g_qal; C = g_q; }
    else if (which == 1) { Ah = g_kah; Al = g_kal; C = g_k; }
    else if (which == 2) { Ah = g_kah; Al = g_kal; C = g_v; }
    else                 { Ah = g_lnh; Al = g_lnl; C = g_mid; resid = g_ln0; mode = 1; }
    const char* Ahc = (const char*)Ah;
    const char* Alc = (const char*)Al;
    const char* Bhc = (const char*)(g_wph + (size_t)which * 65536);
    const char* Blc = (const char*)(g_wpl + (size_t)which * 65536);

    // [2 buf][4 planes: Ah,Al,Bh,Bl][128 rows * 48B] = 48KB
    __shared__ __align__(16) char sm[2][4][128 * 48];

    const int tid  = threadIdx.x;
    const int warp = tid >> 5, lane = tid & 31;
    const int g    = lane >> 2, tg = lane & 3;
    const int wm   = (warp & 3) * 32;
    const int wn   = (warp >> 2) * 64;
    const int nt = blockIdx.x, rt = blockIdx.y;

    float acc[2][8][4];
#pragma unroll
    for (int mf = 0; mf < 2; mf++)
#pragma unroll
        for (int nf = 0; nf < 8; nf++)
#pragma unroll
            for (int q = 0; q < 4; q++) acc[mf][nf][q] = 0.f;

    // cp.async assignment: 64 threads per plane; 256 chunks (128 rows x 2)
    const int plane = tid >> 6, li = tid & 63;
    const char* mysrc = (plane == 0) ? Ahc : (plane == 1) ? Alc
                      : (plane == 2) ? Bhc : Blc;
    const size_t myrow0 = (plane < 2) ? (size_t)rt * 128 : (size_t)nt * 128;

    auto load_step = [&](int ks, int buf) {
        unsigned sb = smem_u32(&sm[buf][plane][0]);
#pragma unroll
        for (int i = 0; i < 4; i++) {
            int idx = li + (i << 6);        // 0..255
            int row = idx >> 1, hh = idx & 1;
            cp16u(sb + row * 48 + hh * 16,
                  mysrc + ((myrow0 + row) * DIM + ks * 16 + hh * 8) * 2);
        }
        cp_commit();
    };

    load_step(0, 0);

    for (int ks = 0; ks < 32; ks++) {
        const int buf = ks & 1;
        if (ks < 31) { load_step(ks + 1, buf ^ 1); cp_wait1(); }
        else         { cp_wait0(); }
        __syncthreads();

        const char* sAh = &sm[buf][0][0];
        const char* sAl = &sm[buf][1][0];
        const char* sBh = &sm[buf][2][0];
        const char* sBl = &sm[buf][3][0];

        // A fragments (canonical m16n8k16 layout, 32-bit LDS)
        unsigned ah[2][4], al[2][4];
#pragma unroll
        for (int mf = 0; mf < 2; mf++) {
            int r0 = wm + mf * 16 + g;
            ah[mf][0] = *(const unsigned*)(sAh + r0 * 48 + tg * 4);
            ah[mf][1] = *(const unsigned*)(sAh + (r0 + 8) * 48 + tg * 4);
            ah[mf][2] = *(const unsigned*)(sAh + r0 * 48 + 16 + tg * 4);
            ah[mf][3] = *(const unsigned*)(sAh + (r0 + 8) * 48 + 16 + tg * 4);
            al[mf][0] = *(const unsigned*)(sAl + r0 * 48 + tg * 4);
            al[mf][1] = *(const unsigned*)(sAl + (r0 + 8) * 48 + tg * 4);
            al[mf][2] = *(const unsigned*)(sAl + r0 * 48 + 16 + tg * 4);
            al[mf][3] = *(const unsigned*)(sAl + (r0 + 8) * 48 + 16 + tg * 4);
        }

#pragma unroll
        for (int nf = 0; nf < 8; nf++) {
            int rn = wn + nf * 8 + g;
            unsigned bh[2], bl[2];
            bh[0] = *(const unsigned*)(sBh + rn * 48 + tg * 4);
            bh[1] = *(const unsigned*)(sBh + rn * 48 + 16 + tg * 4);
            bl[0] = *(const unsigned*)(sBl + rn * 48 + tg * 4);
            bl[1] = *(const unsigned*)(sBl + rn * 48 + 16 + tg * 4);
#pragma unroll
            for (int mf = 0; mf < 2; mf++) {
                mma16816(acc[mf][nf], ah[mf], bh);   // hi*hi
                mma16816(acc[mf][nf], ah[mf], bl);   // hi*lo
                mma16816(acc[mf][nf], al[mf], bh);   // lo*hi
            }
        }
        __syncthreads();
    }

    // epilogue
#pragma unroll
    for (int mf = 0; mf < 2; mf++) {
#pragma unroll
        for (int nf = 0; nf < 8; nf++) {
            int row0 = rt * 128 + wm + mf * 16 + g;
            int row1 = row0 + 8;
            int col  = nt * 128 + wn + nf * 8 + tg * 2;
            float b0 = bias[col], b1 = bias[col + 1];
            float2 o0 = make_float2(acc[mf][nf][0] + b0, acc[mf][nf][1] + b1);
            float2 o1 = make_float2(acc[mf][nf][2] + b0, acc[mf][nf][3] + b1);
            size_t gi0 = (size_t)row0 * DIM + col;
            size_t gi1 = (size_t)row1 * DIM + col;
            if (mode) {
                float2 r0 = *(const float2*)(resid + gi0);
                float2 r1 = *(const float2*)(resid + gi1);
                o0.x = r0.x + fmaxf(o0.x, 0.f);
                o0.y = r0.y + fmaxf(o0.y, 0.f);
                o1.x = r1.x + fmaxf(o1.x, 0.f);
                o1.y = r1.y + fmaxf(o1.y, 0.f);
            }
            *(float2*)(C + gi0) = o0;
            *(float2*)(C + gi1) = o1;
        }
    }
}

// ---------------------------------------------------------------------------
// Flash attention (round-7 proven version, unchanged)
// ---------------------------------------------------------------------------
#define TK 32
#define NT (SEQ / TK)   // 32

__global__ __launch_bounds__(128, 2)
void attn_kernel(const float* __restrict__ pres_q, const float* __restrict__ pres_k)
{
    const int bh = blockIdx.y;
    const int b  = bh >> 3;
    const int h  = bh & 7;
    const int sq = blockIdx.x * 128 + threadIdx.x;
    const int tid = threadIdx.x;

    __shared__ float Ks[2][TK * 64];
    __shared__ float Vs[2][TK * 64];
    __shared__ float pks[2][TK];

    const float* qrow = g_q + ((size_t)b * SEQ + sq) * DIM + h * HDIM;
    u64 q2[32];
#pragma unroll
    for (int i = 0; i < 16; i++) {
        ulonglong2 t = ((const ulonglong2*)qrow)[i];
        q2[2 * i]     = t.x;
        q2[2 * i + 1] = t.y;
    }

    const float INFC  = 1e38f;
    const float rs    = 0.04419417382415922f;
    const float presq = pres_q[b * SEQ + sq];
    const float aq = presq * rs;
    const float cqv = (1.f - presq) * INFC;

    u64 acc2[32];
#pragma unroll
    for (int i = 0; i < 32; i++) acc2[i] = 0ULL;
    float m = -1e38f, l = 0.f;

    const float* kbase = g_k + ((size_t)b * SEQ) * DIM + h * HDIM;
    const float* vbase = g_v + ((size_t)b * SEQ) * DIM + h * HDIM;
    const float* pkb   = pres_k + b * SEQ;

    auto issue_tile = [&](int t, int buf) {
        int k0 = t * TK;
#pragma unroll
        for (int i = 0; i < 4; i++) {
            int f  = tid + 128 * i;
            int j  = f >> 4;
            int c4 = (f & 15) * 4;
            size_t go = (size_t)(k0 + j) * DIM + c4;
            cp16(&Ks[buf][j * 64 + c4], kbase + go);
            cp16(&Vs[buf][j * 64 + c4], vbase + go);
        }
        if (tid < 8) cp16(&pks[buf][tid * 4], pkb + k0 + tid * 4);
        cp_commit();
    };

    issue_tile(0, 0);
    issue_tile(1, 1);

    for (int t = 0; t < NT; ++t) {
        const int buf = t & 1;
        if (t == NT - 1) cp_wait0(); else cp_wait1();
        __syncthreads();

        float s[TK];
#pragma unroll
        for (int j = 0; j < TK; j++) {
            const ulonglong2* kr = (const ulonglong2*)&Ks[buf][j * 64];
            u64 sa = 0ULL, sb = 0ULL;
#pragma unroll
            for (int i = 0; i < 16; i++) {
                ulonglong2 kk = kr[i];
                sa = fma2(q2[2 * i],     kk.x, sa);
                sb = fma2(q2[2 * i + 1], kk.y, sb);
            }
            float lo, hi;
            unpack2(add2(sa, sb), lo, hi);
            float sum = lo + hi;
            float l1  = aq * sum - cqv;
            float pkj = pks[buf][j];
            s[j] = pkj * l1 - (1.f - pkj) * INFC;
        }

        float tm = s[0];
#pragma unroll
        for (int j = 1; j < TK; j++) tm = fmaxf(tm, s[j]);
        float mnew = fmaxf(m, tm);
        bool changed = (mnew != m);
        if (__any_sync(0xffffffffu, changed)) {
            float fac = __expf(m - mnew);
            m = mnew;
            l *= fac;
            u64 facd = dup2(fac);
#pragma unroll
            for (int i = 0; i < 32; i++) acc2[i] = mul2(acc2[i], facd);
        }

#pragma unroll
        for (int j = 0; j < TK; j++) {
            float p = __expf(s[j] - m);
            l += p;
            u64 pd = dup2(p);
            const ulonglong2* vr = (const ulonglong2*)&Vs[buf][j * 64];
#pragma unroll
            for (int i = 0; i < 16; i++) {
                ulonglong2 vv = vr[i];
                acc2[2 * i]     = fma2(pd, vv.x, acc2[2 * i]);
                acc2[2 * i + 1] = fma2(pd, vv.y, acc2[2 * i + 1]);
            }
        }

        __syncthreads();
        if (t + 2 < NT) issue_tile(t + 2, buf);
    }

    float inv = 1.f / l;
    float* orow = g_att + ((size_t)b * SEQ + sq) * DIM + h * HDIM;
#pragma unroll
    for (int i = 0; i < 16; i++) {
        float a0, a1, a2, a3, q0, q1, q2f, q3;
        unpack2(acc2[2 * i],     a0, a1);
        unpack2(acc2[2 * i + 1], a2, a3);
        unpack2(q2[2 * i],       q0, q1);
        unpack2(q2[2 * i + 1],   q2f, q3);
        float4 o;
        o.x = q0  + a0 * inv;
        o.y = q1  + a1 * inv;
        o.z = q2f + a2 * inv;
        o.w = q3  + a3 * inv;
        ((float4*)orow)[i] = o;
    }
}

// ---------------------------------------------------------------------------
// ln0_fused: LayerNorm + fp32 out + row-major bf16 hi/lo planes for o-GEMM
// ---------------------------------------------------------------------------
__global__ __launch_bounds__(128)
void ln0_fused(const float* __restrict__ gg, const float* __restrict__ bb)
{
    const int row = blockIdx.x;
    const int tid = threadIdx.x;

    float4 v = ((const float4*)(g_att + (size_t)row * DIM))[tid];
    float s = v.x + v.y + v.z + v.w;
#pragma unroll
    for (int o = 16; o > 0; o >>= 1) s += __shfl_xor_sync(0xffffffffu, s, o);
    __shared__ float red1[4];
    __shared__ float red2[4];
    int wid = tid >> 5;
    if ((tid & 31) == 0) red1[wid] = s;
    __syncthreads();
    float mu = (red1[0] + red1[1] + red1[2] + red1[3]) * (1.f / DIM);

    float dx = v.x - mu, dy = v.y - mu, dz = v.z - mu, dw = v.w - mu;
    float q = dx * dx + dy * dy + dz * dz + dw * dw;
#pragma unroll
    for (int o = 16; o > 0; o >>= 1) q += __shfl_xor_sync(0xffffffffu, q, o);
    if ((tid & 31) == 0) red2[wid] = q;
    __syncthreads();
    float var  = (red2[0] + red2[1] + red2[2] + red2[3]) * (1.f / DIM);
    float rstd = rsqrtf(var + 1e-5f);

    float4 gv = ((const float4*)gg)[tid];
    float4 bv = ((const float4*)bb)[tid];
    float4 o;
    o.x = dx * rstd * gv.x + bv.x;
    o.y = dy * rstd * gv.y + bv.y;
    o.z = dz * rstd * gv.z + bv.z;
    o.w = dw * rstd * gv.w + bv.w;
    ((float4*)(g_ln0 + (size_t)row * DIM))[tid] = o;

    uint2 h, l;
    split4(o, h, l);
    size_t pi = (size_t)row * 128 + tid;
    g_lnh[pi] = h;
    g_lnl[pi] = l;
}

// ---------------------------------------------------------------------------
// LayerNorm 1 -> output
// ---------------------------------------------------------------------------
__global__ __launch_bounds__(128)
void ln1_kernel(const float* __restrict__ g, const float* __restrict__ b,
                float* __restrict__ out)
{
    const int row = blockIdx.x;
    const int tid = threadIdx.x;
    const float* x = g_mid + (size_t)row * DIM;

    float v[4];
#pragma unroll
    for (int i = 0; i < 4; i++) v[i] = x[tid + i * 128];

    float s = v[0] + v[1] + v[2] + v[3];
#pragma unroll
    for (int o = 16; o > 0; o >>= 1) s += __shfl_xor_sync(0xffffffffu, s, o);
    __shared__ float red1[4];
    __shared__ float red2[4];
    int wid = tid >> 5;
    if ((tid & 31) == 0) red1[wid] = s;
    __syncthreads();
    float mu = (red1[0] + red1[1] + red1[2] + red1[3]) * (1.f / DIM);

    float q = 0.f;
#pragma unroll
    for (int i = 0; i < 4; i++) { float d = v[i] - mu; q += d * d; }
#pragma unroll
    for (int o = 16; o > 0; o >>= 1) q += __shfl_xor_sync(0xffffffffu, q, o);
    if ((tid & 31) == 0) red2[wid] = q;
    __syncthreads();
    float var  = (red2[0] + red2[1] + red2[2] + red2[3]) * (1.f / DIM);
    float rstd = rsqrtf(var + 1e-5f);

#pragma unroll
    for (int i = 0; i < 4; i++) {
        int c = tid + i * 128;
        out[(size_t)row * DIM + c] = (v[i] - mu) * rstd * g[c] + b[c];
    }
}

// ---------------------------------------------------------------------------
extern "C" void kernel_launch(void* const* d_in, const int* in_sizes, int n_in,
                              void* d_out, int out_size)
{
    const float* queries = (const float*)d_in[0];
    const float* keys    = (const float*)d_in[1];
    const float* pq      = (const float*)d_in[2];
    const float* pk      = (const float*)d_in[3];

    int base = 4;
    if (n_in >= 5 && in_sizes[4] == 1) base = 5;

    const float* Wq = (const float*)d_in[base + 0];
    const float* bq = (const float*)d_in[base + 1];
    const float* Wk = (const float*)d_in[base + 2];
    const float* bk = (const float*)d_in[base + 3];
    const float* Wv = (const float*)d_in[base + 4];
    const float* bv = (const float*)d_in[base + 5];
    const float* Wo = (const float*)d_in[base + 6];
    const float* bo = (const float*)d_in[base + 7];
    const float* g0 = (const float*)d_in[base + 8];
    const float* b0 = (const float*)d_in[base + 9];
    const float* g1 = (const float*)d_in[base + 10];
    const float* b1 = (const float*)d_in[base + 11];
    float* out = (float*)d_out;

    convert_w<<<dim3(256, 4), 256>>>(Wq, Wk, Wv, Wo);
    convert_a<<<4096, 256>>>(queries, 0);
    convert_a<<<4096, 256>>>(keys, 1);

    mma_gemm<<<dim3(4, 64), 256>>>(0, bq);
    mma_gemm<<<dim3(4, 64), 256>>>(1, bk);
    mma_gemm<<<dim3(4, 64), 256>>>(2, bv);

    attn_kernel<<<dim3(SEQ / 128, BSZ * NHEAD), 128>>>(pq, pk);
    ln0_fused<<<NTOK, 128>>>(g0, b0);
    mma_gemm<<<dim3(4, 64), 256>>>(3, bo);
    ln1_kernel<<<NTOK, 128>>>(g1, b1, out);
}

// round 10
// speedup vs baseline: 2.6319x; 1.5626x over previous
#include <cuda_runtime.h>
#include <cuda_bf16.h>
#include <cstdint>

#define BSZ 8
#define SEQ 1024
#define DIM 512
#define NHEAD 8
#define HDIM 64
#define NTOK (BSZ*SEQ)                 // 8192
#define NELEM ((size_t)NTOK*DIM)       // 4194304

// fp32 intermediates
__device__ float g_q[NELEM];
__device__ float g_k[NELEM];
__device__ float g_v[NELEM];
__device__ float g_att[NELEM];
__device__ float g_ln0[NELEM];
__device__ float g_mid[NELEM];

// bf16 split planes, ROW-MAJOR. uint2 = 4 bf16.
__device__ uint2 g_qah[NELEM/4], g_qal[NELEM/4];
__device__ uint2 g_kah[NELEM/4], g_kal[NELEM/4];
__device__ uint2 g_lnh[NELEM/4], g_lnl[NELEM/4];
__device__ uint2 g_wph[4*DIM*DIM/4], g_wpl[4*DIM*DIM/4];   // B[n][k] = W[k][n]

typedef unsigned long long u64;

// ---------------------------------------------------------------------------
// cp.async helpers
// ---------------------------------------------------------------------------
__device__ __forceinline__ void cp16u(unsigned int saddr, const void* gmem_src) {
    asm volatile("cp.async.cg.shared.global [%0], [%1], 16;"
                 :: "r"(saddr), "l"(gmem_src) : "memory");
}
__device__ __forceinline__ void cp_commit() {
    asm volatile("cp.async.commit_group;" ::: "memory");
}
__device__ __forceinline__ void cp_wait0() {
    asm volatile("cp.async.wait_group 0;" ::: "memory");
}
__device__ __forceinline__ void cp_wait1() {
    asm volatile("cp.async.wait_group 1;" ::: "memory");
}
__device__ __forceinline__ unsigned smem_u32(const void* p) {
    unsigned r;
    asm("{ .reg .u64 t; cvta.to.shared.u64 t, %1; cvt.u32.u64 %0, t; }"
        : "=r"(r) : "l"(p));
    return r;
}

// ---------------------------------------------------------------------------
// warp-level bf16 MMA (sm_80+ instruction, valid on base sm_103 target)
// ---------------------------------------------------------------------------
__device__ __forceinline__ void mma16816(float* d, const unsigned* a, const unsigned* b) {
    asm volatile(
        "mma.sync.aligned.m16n8k16.row.col.f32.bf16.bf16.f32 "
        "{%0,%1,%2,%3}, {%4,%5,%6,%7}, {%8,%9}, {%0,%1,%2,%3};"
        : "+f"(d[0]), "+f"(d[1]), "+f"(d[2]), "+f"(d[3])
        : "r"(a[0]), "r"(a[1]), "r"(a[2]), "r"(a[3]), "r"(b[0]), "r"(b[1]));
}

// bf16 split helpers
__device__ __forceinline__ void split2(float2 x, unsigned& h, unsigned& l) {
    __nv_bfloat162 hh = __floats2bfloat162_rn(x.x, x.y);
    float r0 = x.x - __bfloat162float(__low2bfloat16(hh));
    float r1 = x.y - __bfloat162float(__high2bfloat16(hh));
    __nv_bfloat162 ll = __floats2bfloat162_rn(r0, r1);
    h = *(unsigned*)&hh; l = *(unsigned*)&ll;
}
__device__ __forceinline__ void split4(float4 x, uint2& h, uint2& l) {
    unsigned h0, l0, h1, l1;
    split2(make_float2(x.x, x.y), h0, l0);
    split2(make_float2(x.z, x.w), h1, l1);
    h = make_uint2(h0, h1);
    l = make_uint2(l0, l1);
}

// ---------------------------------------------------------------------------
// convert_a / convert_w (unchanged from round 9)
// ---------------------------------------------------------------------------
__global__ __launch_bounds__(256)
void convert_a(const float* __restrict__ A, int dst)
{
    uint2* H = dst ? g_kah : g_qah;
    uint2* L = dst ? g_kal : g_qal;
    size_t i = (size_t)blockIdx.x * 256 + threadIdx.x;
    float4 x = ((const float4*)A)[i];
    uint2 h, l;
    split4(x, h, l);
    H[i] = h;
    L[i] = l;
}

__global__ __launch_bounds__(256)
void convert_w(const float* __restrict__ Wq, const float* __restrict__ Wk,
               const float* __restrict__ Wv, const float* __restrict__ Wo)
{
    const int mat = blockIdx.y;
    const float* W = (mat == 0) ? Wq : (mat == 1) ? Wk : (mat == 2) ? Wv : Wo;
    int o = blockIdx.x * 256 + threadIdx.x;
    int n  = o >> 7;
    int k0 = (o & 127) * 4;
    float4 x;
    x.x = W[(size_t)(k0 + 0) * DIM + n];
    x.y = W[(size_t)(k0 + 1) * DIM + n];
    x.z = W[(size_t)(k0 + 2) * DIM + n];
    x.w = W[(size_t)(k0 + 3) * DIM + n];
    uint2 h, l;
    split4(x, h, l);
    g_wph[(size_t)mat * 65536 + o] = h;
    g_wpl[(size_t)mat * 65536 + o] = l;
}

// ---------------------------------------------------------------------------
// Tensor-core GEMM (round-9 proven version, unchanged)
// ---------------------------------------------------------------------------
__global__ __launch_bounds__(256)
void mma_gemm(int which, const float* __restrict__ bias)
{
    const uint2 *Ah, *Al; float* C;
    const float* resid = nullptr; int mode = 0;
    if (which == 0)      { Ah = g_qah; Al = g_qal; C = g_q; }
    else if (which == 1) { Ah = g_kah; Al = g_kal; C = g_k; }
    else if (which == 2) { Ah = g_kah; Al = g_kal; C = g_v; }
    else                 { Ah = g_lnh; Al = g_lnl; C = g_mid; resid = g_ln0; mode = 1; }
    const char* Ahc = (const char*)Ah;
    const char* Alc = (const char*)Al;
    const char* Bhc = (const char*)(g_wph + (size_t)which * 65536);
    const char* Blc = (const char*)(g_wpl + (size_t)which * 65536);

    __shared__ __align__(16) char sm[2][4][128 * 48];

    const int tid  = threadIdx.x;
    const int warp = tid >> 5, lane = tid & 31;
    const int g    = lane >> 2, tg = lane & 3;
    const int wm   = (warp & 3) * 32;
    const int wn   = (warp >> 2) * 64;
    const int nt = blockIdx.x, rt = blockIdx.y;

    float acc[2][8][4];
#pragma unroll
    for (int mf = 0; mf < 2; mf++)
#pragma unroll
        for (int nf = 0; nf < 8; nf++)
#pragma unroll
            for (int q = 0; q < 4; q++) acc[mf][nf][q] = 0.f;

    const int plane = tid >> 6, li = tid & 63;
    const char* mysrc = (plane == 0) ? Ahc : (plane == 1) ? Alc
                      : (plane == 2) ? Bhc : Blc;
    const size_t myrow0 = (plane < 2) ? (size_t)rt * 128 : (size_t)nt * 128;

    auto load_step = [&](int ks, int buf) {
        unsigned sb = smem_u32(&sm[buf][plane][0]);
#pragma unroll
        for (int i = 0; i < 4; i++) {
            int idx = li + (i << 6);
            int row = idx >> 1, hh = idx & 1;
            cp16u(sb + row * 48 + hh * 16,
                  mysrc + ((myrow0 + row) * DIM + ks * 16 + hh * 8) * 2);
        }
        cp_commit();
    };

    load_step(0, 0);

    for (int ks = 0; ks < 32; ks++) {
        const int buf = ks & 1;
        if (ks < 31) { load_step(ks + 1, buf ^ 1); cp_wait1(); }
        else         { cp_wait0(); }
        __syncthreads();

        const char* sAh = &sm[buf][0][0];
        const char* sAl = &sm[buf][1][0];
        const char* sBh = &sm[buf][2][0];
        const char* sBl = &sm[buf][3][0];

        unsigned ah[2][4], al[2][4];
#pragma unroll
        for (int mf = 0; mf < 2; mf++) {
            int r0 = wm + mf * 16 + g;
            ah[mf][0] = *(const unsigned*)(sAh + r0 * 48 + tg * 4);
            ah[mf][1] = *(const unsigned*)(sAh + (r0 + 8) * 48 + tg * 4);
            ah[mf][2] = *(const unsigned*)(sAh + r0 * 48 + 16 + tg * 4);
            ah[mf][3] = *(const unsigned*)(sAh + (r0 + 8) * 48 + 16 + tg * 4);
            al[mf][0] = *(const unsigned*)(sAl + r0 * 48 + tg * 4);
            al[mf][1] = *(const unsigned*)(sAl + (r0 + 8) * 48 + tg * 4);
            al[mf][2] = *(const unsigned*)(sAl + r0 * 48 + 16 + tg * 4);
            al[mf][3] = *(const unsigned*)(sAl + (r0 + 8) * 48 + 16 + tg * 4);
        }

#pragma unroll
        for (int nf = 0; nf < 8; nf++) {
            int rn = wn + nf * 8 + g;
            unsigned bh[2], bl[2];
            bh[0] = *(const unsigned*)(sBh + rn * 48 + tg * 4);
            bh[1] = *(const unsigned*)(sBh + rn * 48 + 16 + tg * 4);
            bl[0] = *(const unsigned*)(sBl + rn * 48 + tg * 4);
            bl[1] = *(const unsigned*)(sBl + rn * 48 + 16 + tg * 4);
#pragma unroll
            for (int mf = 0; mf < 2; mf++) {
                mma16816(acc[mf][nf], ah[mf], bh);
                mma16816(acc[mf][nf], ah[mf], bl);
                mma16816(acc[mf][nf], al[mf], bh);
            }
        }
        __syncthreads();
    }

#pragma unroll
    for (int mf = 0; mf < 2; mf++) {
#pragma unroll
        for (int nf = 0; nf < 8; nf++) {
            int row0 = rt * 128 + wm + mf * 16 + g;
            int row1 = row0 + 8;
            int col  = nt * 128 + wn + nf * 8 + tg * 2;
            float b0 = bias[col], b1 = bias[col + 1];
            float2 o0 = make_float2(acc[mf][nf][0] + b0, acc[mf][nf][1] + b1);
            float2 o1 = make_float2(acc[mf][nf][2] + b0, acc[mf][nf][3] + b1);
            size_t gi0 = (size_t)row0 * DIM + col;
            size_t gi1 = (size_t)row1 * DIM + col;
            if (mode) {
                float2 r0 = *(const float2*)(resid + gi0);
                float2 r1 = *(const float2*)(resid + gi1);
                o0.x = r0.x + fmaxf(o0.x, 0.f);
                o0.y = r0.y + fmaxf(o0.y, 0.f);
                o1.x = r1.x + fmaxf(o1.x, 0.f);
                o1.y = r1.y + fmaxf(o1.y, 0.f);
            }
            *(float2*)(C + gi0) = o0;
            *(float2*)(C + gi1) = o1;
        }
    }
}

// ---------------------------------------------------------------------------
// Tensor-core flash attention.
// Block = (b,h) x 128 q rows; 8 warps x 16 rows; 64-key tiles.
// S = QK^T via 3-term bf16 split; P packed in-register from S frags (FA2
// layout identity); PV via 3-term split with V transposed in smem.
// XOR-16B swizzle on K/V smem rows -> conflict-free fragment LDS.
// ---------------------------------------------------------------------------
__global__ __launch_bounds__(256)
void attn_mma(const float* __restrict__ pres_q, const float* __restrict__ pres_k)
{
    __shared__ __align__(16) char sm[33024];
    char* sKh = sm;
    char* sKl = sm + 8192;
    char* sVh = sm + 16384;
    char* sVl = sm + 24576;
    float* pks = (float*)(sm + 32768);

    const int tid  = threadIdx.x;
    const int warp = tid >> 5, lane = tid & 31;
    const int g = lane >> 2, tg = lane & 3;
    const int bh = blockIdx.y, b = bh >> 3, h = bh & 7;
    const int q0 = blockIdx.x * 128;
    const int r0 = q0 + warp * 16 + g;
    const int r1 = r0 + 8;

    // Q fragments (hi/lo), rows r0/r1, k = d (4 frags of k16)
    unsigned qh[4][4], ql[4][4];
    {
        const float* Q0 = g_q + (size_t)(b * SEQ + r0) * DIM + h * HDIM;
        const float* Q1 = g_q + (size_t)(b * SEQ + r1) * DIM + h * HDIM;
#pragma unroll
        for (int kf = 0; kf < 4; kf++) {
            split2(*(const float2*)(Q0 + kf * 16 + 2 * tg),     qh[kf][0], ql[kf][0]);
            split2(*(const float2*)(Q1 + kf * 16 + 2 * tg),     qh[kf][1], ql[kf][1]);
            split2(*(const float2*)(Q0 + kf * 16 + 8 + 2 * tg), qh[kf][2], ql[kf][2]);
            split2(*(const float2*)(Q1 + kf * 16 + 8 + 2 * tg), qh[kf][3], ql[kf][3]);
        }
    }

    const float INFC = 1e38f;
    const float rs   = 0.04419417382415922f;   // 1/sqrt(512)
    const float pq0v = pres_q[b * SEQ + r0];
    const float pq1v = pres_q[b * SEQ + r1];
    const float aq0 = pq0v * rs, cq0 = (1.f - pq0v) * INFC;
    const float aq1 = pq1v * rs, cq1 = (1.f - pq1v) * INFC;

    float m0 = -1e38f, l0 = 0.f, m1 = -1e38f, l1 = 0.f;
    float O[8][4];
#pragma unroll
    for (int nf = 0; nf < 8; nf++)
#pragma unroll
        for (int q = 0; q < 4; q++) O[nf][q] = 0.f;

    for (int t = 0; t < SEQ / 64; t++) {
        __syncthreads();   // prior tile reads complete
        // ---- convert K/V tile to bf16 hi/lo smem (V transposed) ----
        {
            const int key = tid >> 2;
            const int dq  = (tid & 3) * 16;
            const size_t gro = (size_t)(b * SEQ + t * 64 + key) * DIM + h * HDIM + dq;
            float4 k0v = *(const float4*)(g_k + gro);
            float4 k1v = *(const float4*)(g_k + gro + 4);
            float4 k2v = *(const float4*)(g_k + gro + 8);
            float4 k3v = *(const float4*)(g_k + gro + 12);
            float4 v0v = *(const float4*)(g_v + gro);
            float4 v1v = *(const float4*)(g_v + gro + 4);
            float4 v2v = *(const float4*)(g_v + gro + 8);
            float4 v3v = *(const float4*)(g_v + gro + 12);
            float kf_[16] = {k0v.x,k0v.y,k0v.z,k0v.w, k1v.x,k1v.y,k1v.z,k1v.w,
                             k2v.x,k2v.y,k2v.z,k2v.w, k3v.x,k3v.y,k3v.z,k3v.w};
            float vf_[16] = {v0v.x,v0v.y,v0v.z,v0v.w, v1v.x,v1v.y,v1v.z,v1v.w,
                             v2v.x,v2v.y,v2v.z,v2v.w, v3v.x,v3v.y,v3v.z,v3v.w};
            const int ksw = (key & 7) << 4;
#pragma unroll
            for (int j = 0; j < 8; j++) {
                unsigned hh, ll;
                split2(make_float2(kf_[2 * j], kf_[2 * j + 1]), hh, ll);
                int c = (2 * dq + 4 * j) ^ ksw;
                *(unsigned*)(sKh + key * 128 + c) = hh;
                *(unsigned*)(sKl + key * 128 + c) = ll;
            }
#pragma unroll
            for (int i = 0; i < 16; i++) {
                int d = dq + i;
                float v = vf_[i];
                __nv_bfloat16 hb = __float2bfloat16(v);
                float rr = v - __bfloat162float(hb);
                __nv_bfloat16 lb = __float2bfloat16(rr);
                int c = (2 * key) ^ ((d & 7) << 4);
                *(__nv_bfloat16*)(sVh + d * 128 + c) = hb;
                *(__nv_bfloat16*)(sVl + d * 128 + c) = lb;
            }
            if (tid < 64) pks[tid] = pres_k[b * SEQ + t * 64 + tid];
        }
        __syncthreads();

        // ---- S = Q K^T (3-term split) ----
        float S[8][4];
#pragma unroll
        for (int nf = 0; nf < 8; nf++)
#pragma unroll
            for (int q = 0; q < 4; q++) S[nf][q] = 0.f;

        const int sw = g << 4;
#pragma unroll
        for (int nf = 0; nf < 8; nf++) {
            const int ro = (nf * 8 + g) * 128;
#pragma unroll
            for (int kf = 0; kf < 4; kf++) {
                unsigned bh2[2], bl2[2];
                bh2[0] = *(unsigned*)(sKh + ro + ((32 * kf + 4 * tg) ^ sw));
                bh2[1] = *(unsigned*)(sKh + ro + ((32 * kf + 16 + 4 * tg) ^ sw));
                bl2[0] = *(unsigned*)(sKl + ro + ((32 * kf + 4 * tg) ^ sw));
                bl2[1] = *(unsigned*)(sKl + ro + ((32 * kf + 16 + 4 * tg) ^ sw));
                mma16816(S[nf], qh[kf], bh2);
                mma16816(S[nf], qh[kf], bl2);
                mma16816(S[nf], ql[kf], bh2);
            }
        }

        // ---- mask + streaming softmax ----
        float tmax0 = -1e38f, tmax1 = -1e38f;
#pragma unroll
        for (int nf = 0; nf < 8; nf++) {
            float2 pk2 = *(const float2*)(pks + nf * 8 + 2 * tg);
            S[nf][0] = pk2.x * (aq0 * S[nf][0] - cq0) - (1.f - pk2.x) * INFC;
            S[nf][1] = pk2.y * (aq0 * S[nf][1] - cq0) - (1.f - pk2.y) * INFC;
            S[nf][2] = pk2.x * (aq1 * S[nf][2] - cq1) - (1.f - pk2.x) * INFC;
            S[nf][3] = pk2.y * (aq1 * S[nf][3] - cq1) - (1.f - pk2.y) * INFC;
            tmax0 = fmaxf(tmax0, fmaxf(S[nf][0], S[nf][1]));
            tmax1 = fmaxf(tmax1, fmaxf(S[nf][2], S[nf][3]));
        }
        tmax0 = fmaxf(tmax0, __shfl_xor_sync(0xffffffffu, tmax0, 1));
        tmax0 = fmaxf(tmax0, __shfl_xor_sync(0xffffffffu, tmax0, 2));
        tmax1 = fmaxf(tmax1, __shfl_xor_sync(0xffffffffu, tmax1, 1));
        tmax1 = fmaxf(tmax1, __shfl_xor_sync(0xffffffffu, tmax1, 2));
        float mn0 = fmaxf(m0, tmax0);
        float mn1 = fmaxf(m1, tmax1);
        bool ch = (mn0 != m0) || (mn1 != m1);
        if (__any_sync(0xffffffffu, ch)) {
            float f0 = __expf(m0 - mn0);
            float f1 = __expf(m1 - mn1);
            m0 = mn0; m1 = mn1;
            l0 *= f0;  l1 *= f1;
#pragma unroll
            for (int nf = 0; nf < 8; nf++) {
                O[nf][0] *= f0; O[nf][1] *= f0;
                O[nf][2] *= f1; O[nf][3] *= f1;
            }
        }
#pragma unroll
        for (int nf = 0; nf < 8; nf++) {
            S[nf][0] = __expf(S[nf][0] - m0); l0 += S[nf][0];
            S[nf][1] = __expf(S[nf][1] - m0); l0 += S[nf][1];
            S[nf][2] = __expf(S[nf][2] - m1); l1 += S[nf][2];
            S[nf][3] = __expf(S[nf][3] - m1); l1 += S[nf][3];
        }

        // ---- O += P V (3-term split); P frags packed from S frags ----
#pragma unroll
        for (int kfp = 0; kfp < 4; kfp++) {
            const int na = 2 * kfp, nb = na + 1;
            unsigned ph[4], pl[4];
            split2(make_float2(S[na][0], S[na][1]), ph[0], pl[0]);
            split2(make_float2(S[na][2], S[na][3]), ph[1], pl[1]);
            split2(make_float2(S[nb][0], S[nb][1]), ph[2], pl[2]);
            split2(make_float2(S[nb][2], S[nb][3]), ph[3], pl[3]);
#pragma unroll
            for (int nf = 0; nf < 8; nf++) {
                const int ro = (nf * 8 + g) * 128;
                unsigned vh2[2], vl2[2];
                vh2[0] = *(unsigned*)(sVh + ro + ((32 * kfp + 4 * tg) ^ sw));
                vh2[1] = *(unsigned*)(sVh + ro + ((32 * kfp + 16 + 4 * tg) ^ sw));
                vl2[0] = *(unsigned*)(sVl + ro + ((32 * kfp + 4 * tg) ^ sw));
                vl2[1] = *(unsigned*)(sVl + ro + ((32 * kfp + 16 + 4 * tg) ^ sw));
                mma16816(O[nf], ph, vh2);
                mma16816(O[nf], ph, vl2);
                mma16816(O[nf], pl, vh2);
            }
        }
    }

    // ---- epilogue: o = q + O / l ----
    l0 += __shfl_xor_sync(0xffffffffu, l0, 1);
    l0 += __shfl_xor_sync(0xffffffffu, l0, 2);
    l1 += __shfl_xor_sync(0xffffffffu, l1, 1);
    l1 += __shfl_xor_sync(0xffffffffu, l1, 2);
    float inv0 = 1.f / l0;
    float inv1 = 1.f / l1;
#pragma unroll
    for (int nf = 0; nf < 8; nf++) {
        int col = h * HDIM + nf * 8 + 2 * tg;
        size_t gi0 = (size_t)(b * SEQ + r0) * DIM + col;
        size_t gi1 = (size_t)(b * SEQ + r1) * DIM + col;
        float2 qv0 = *(const float2*)(g_q + gi0);
        float2 qv1 = *(const float2*)(g_q + gi1);
        float2 o0 = make_float2(qv0.x + O[nf][0] * inv0, qv0.y + O[nf][1] * inv0);
        float2 o1 = make_float2(qv1.x + O[nf][2] * inv1, qv1.y + O[nf][3] * inv1);
        *(float2*)(g_att + gi0) = o0;
        *(float2*)(g_att + gi1) = o1;
    }
}

// ---------------------------------------------------------------------------
// ln0_fused: LayerNorm + fp32 out + row-major bf16 hi/lo planes for o-GEMM
// ---------------------------------------------------------------------------
__global__ __launch_bounds__(128)
void ln0_fused(const float* __restrict__ gg, const float* __restrict__ bb)
{
    const int row = blockIdx.x;
    const int tid = threadIdx.x;

    float4 v = ((const float4*)(g_att + (size_t)row * DIM))[tid];
    float s = v.x + v.y + v.z + v.w;
#pragma unroll
    for (int o = 16; o > 0; o >>= 1) s += __shfl_xor_sync(0xffffffffu, s, o);
    __shared__ float red1[4];
    __shared__ float red2[4];
    int wid = tid >> 5;
    if ((tid & 31) == 0) red1[wid] = s;
    __syncthreads();
    float mu = (red1[0] + red1[1] + red1[2] + red1[3]) * (1.f / DIM);

    float dx = v.x - mu, dy = v.y - mu, dz = v.z - mu, dw = v.w - mu;
    float q = dx * dx + dy * dy + dz * dz + dw * dw;
#pragma unroll
    for (int o = 16; o > 0; o >>= 1) q += __shfl_xor_sync(0xffffffffu, q, o);
    if ((tid & 31) == 0) red2[wid] = q;
    __syncthreads();
    float var  = (red2[0] + red2[1] + red2[2] + red2[3]) * (1.f / DIM);
    float rstd = rsqrtf(var + 1e-5f);

    float4 gv = ((const float4*)gg)[tid];
    float4 bv = ((const float4*)bb)[tid];
    float4 o;
    o.x = dx * rstd * gv.x + bv.x;
    o.y = dy * rstd * gv.y + bv.y;
    o.z = dz * rstd * gv.z + bv.z;
    o.w = dw * rstd * gv.w + bv.w;
    ((float4*)(g_ln0 + (size_t)row * DIM))[tid] = o;

    uint2 h, l;
    split4(o, h, l);
    size_t pi = (size_t)row * 128 + tid;
    g_lnh[pi] = h;
    g_lnl[pi] = l;
}

// ---------------------------------------------------------------------------
// LayerNorm 1 -> output
// ---------------------------------------------------------------------------
__global__ __launch_bounds__(128)
void ln1_kernel(const float* __restrict__ g, const float* __restrict__ b,
                float* __restrict__ out)
{
    const int row = blockIdx.x;
    const int tid = threadIdx.x;
    const float* x = g_mid + (size_t)row * DIM;

    float v[4];
#pragma unroll
    for (int i = 0; i < 4; i++) v[i] = x[tid + i * 128];

    float s = v[0] + v[1] + v[2] + v[3];
#pragma unroll
    for (int o = 16; o > 0; o >>= 1) s += __shfl_xor_sync(0xffffffffu, s, o);
    __shared__ float red1[4];
    __shared__ float red2[4];
    int wid = tid >> 5;
    if ((tid & 31) == 0) red1[wid] = s;
    __syncthreads();
    float mu = (red1[0] + red1[1] + red1[2] + red1[3]) * (1.f / DIM);

    float q = 0.f;
#pragma unroll
    for (int i = 0; i < 4; i++) { float d = v[i] - mu; q += d * d; }
#pragma unroll
    for (int o = 16; o > 0; o >>= 1) q += __shfl_xor_sync(0xffffffffu, q, o);
    if ((tid & 31) == 0) red2[wid] = q;
    __syncthreads();
    float var  = (red2[0] + red2[1] + red2[2] + red2[3]) * (1.f / DIM);
    float rstd = rsqrtf(var + 1e-5f);

#pragma unroll
    for (int i = 0; i < 4; i++) {
        int c = tid + i * 128;
        out[(size_t)row * DIM + c] = (v[i] - mu) * rstd * g[c] + b[c];
    }
}

// ---------------------------------------------------------------------------
extern "C" void kernel_launch(void* const* d_in, const int* in_sizes, int n_in,
                              void* d_out, int out_size)
{
    const float* queries = (const float*)d_in[0];
    const float* keys    = (const float*)d_in[1];
    const float* pq      = (const float*)d_in[2];
    const float* pk      = (const float*)d_in[3];

    int base = 4;
    if (n_in >= 5 && in_sizes[4] == 1) base = 5;

    const float* Wq = (const float*)d_in[base + 0];
    const float* bq = (const float*)d_in[base + 1];
    const float* Wk = (const float*)d_in[base + 2];
    const float* bk = (const float*)d_in[base + 3];
    const float* Wv = (const float*)d_in[base + 4];
    const float* bv = (const float*)d_in[base + 5];
    const float* Wo = (const float*)d_in[base + 6];
    const float* bo = (const float*)d_in[base + 7];
    const float* g0 = (const float*)d_in[base + 8];
    const float* b0 = (const float*)d_in[base + 9];
    const float* g1 = (const float*)d_in[base + 10];
    const float* b1 = (const float*)d_in[base + 11];
    float* out = (float*)d_out;

    convert_w<<<dim3(256, 4), 256>>>(Wq, Wk, Wv, Wo);
    convert_a<<<4096, 256>>>(queries, 0);
    convert_a<<<4096, 256>>>(keys, 1);

    mma_gemm<<<dim3(4, 64), 256>>>(0, bq);
    mma_gemm<<<dim3(4, 64), 256>>>(1, bk);
    mma_gemm<<<dim3(4, 64), 256>>>(2, bv);

    attn_mma<<<dim3(SEQ / 128, BSZ * NHEAD), 256>>>(pq, pk);
    ln0_fused<<<NTOK, 128>>>(g0, b0);
    mma_gemm<<<dim3(4, 64), 256>>>(3, bo);
    ln1_kernel<<<NTOK, 128>>>(g1, b1, out);
}